// round 2
// baseline (speedup 1.0000x reference)
#include <cuda_runtime.h>
#include <math.h>

#define N_ROIS 2000
#define IN_F   12544
#define REP    1024
#define NCLS   91
#define NC1    90
#define TOT    (N_ROIS * NC1)          // 180000
#define MAXC   40960
#define NEGV   (-1e10f)
#define BBOX_CLIP_F 4.135166556742356f
#define MAXDET 100

// ------------------------- scratch (static, no allocs) -------------------------
__device__ float g_h1[N_ROIS * REP];
__device__ float g_h2[N_ROIS * REP];
__device__ float g_logits[N_ROIS * NCLS];
__device__ float g_breg[N_ROIS * 4 * NCLS];
__device__ float g_scores[N_ROIS * NCLS];
__device__ float g_dbox[TOT * 4];
__device__ unsigned char g_valid[TOT];
__device__ float g_cbox[MAXC * 4];
__device__ float g_obox[MAXC * 4];
__device__ float g_csm[MAXC];
__device__ float g_cscore[MAXC];
__device__ int   g_clabel[MAXC];
__device__ int   g_ccount;
__device__ int   g_keep[MAXDET];

// ------------------------- SGEMM: C = act(A*B + bias) -------------------------
// A [M,K] row-major, B [K,N] row-major. BM=BN=128, BK=8, 256 threads, 8x8 microtile.
// K must be a multiple of 8 and 4-aligned rows for A (true here: 12544, 1024).
__global__ void __launch_bounds__(256, 2) sgemm_bias_act(
    const float* __restrict__ A, const float* __restrict__ B,
    const float* __restrict__ bias, float* __restrict__ C,
    int M, int N, int K, int relu)
{
    __shared__ float As[8][128];
    __shared__ float Bs[8][128];

    const int tid  = threadIdx.x;
    const int bm   = blockIdx.y * 128;
    const int bn   = blockIdx.x * 128;

    const int arow = tid >> 1;          // 0..127
    const int acol = (tid & 1) * 4;     // 0 or 4
    const int brow = tid >> 5;          // 0..7
    const int bcol = (tid & 31) * 4;    // 0..124

    const int tx = tid & 15;
    const int ty = tid >> 4;

    const bool arow_ok = (bm + arow) < M;
    const bool nvec    = ((N & 3) == 0);

    float acc[8][8];
#pragma unroll
    for (int i = 0; i < 8; ++i)
#pragma unroll
        for (int j = 0; j < 8; ++j) acc[i][j] = 0.f;

    const float* aBase = A + (size_t)(bm + arow) * K + acol;

    // prefetch regs
    float a0 = 0, a1 = 0, a2 = 0, a3 = 0;
    float b0 = 0, b1 = 0, b2 = 0, b3 = 0;

    // load tile k0 = 0
    if (arow_ok) {
        float4 t = *reinterpret_cast<const float4*>(aBase);
        a0 = t.x; a1 = t.y; a2 = t.z; a3 = t.w;
    }
    {
        const float* bp = B + (size_t)brow * N + bn + bcol;
        if (nvec) {
            if (bn + bcol < N) {
                float4 t = *reinterpret_cast<const float4*>(bp);
                b0 = t.x; b1 = t.y; b2 = t.z; b3 = t.w;
            }
        } else {
            b0 = (bn + bcol + 0 < N) ? bp[0] : 0.f;
            b1 = (bn + bcol + 1 < N) ? bp[1] : 0.f;
            b2 = (bn + bcol + 2 < N) ? bp[2] : 0.f;
            b3 = (bn + bcol + 3 < N) ? bp[3] : 0.f;
        }
    }

    for (int k0 = 0; k0 < K; k0 += 8) {
        // commit prefetched tile to smem
        As[acol + 0][arow] = a0;
        As[acol + 1][arow] = a1;
        As[acol + 2][arow] = a2;
        As[acol + 3][arow] = a3;
        Bs[brow][bcol + 0] = b0;
        Bs[brow][bcol + 1] = b1;
        Bs[brow][bcol + 2] = b2;
        Bs[brow][bcol + 3] = b3;
        __syncthreads();

        // prefetch next tile
        const int kn = k0 + 8;
        if (kn < K) {
            if (arow_ok) {
                float4 t = *reinterpret_cast<const float4*>(aBase + kn);
                a0 = t.x; a1 = t.y; a2 = t.z; a3 = t.w;
            }
            const float* bp = B + (size_t)(kn + brow) * N + bn + bcol;
            if (nvec) {
                if (bn + bcol < N) {
                    float4 t = *reinterpret_cast<const float4*>(bp);
                    b0 = t.x; b1 = t.y; b2 = t.z; b3 = t.w;
                }
            } else {
                b0 = (bn + bcol + 0 < N) ? bp[0] : 0.f;
                b1 = (bn + bcol + 1 < N) ? bp[1] : 0.f;
                b2 = (bn + bcol + 2 < N) ? bp[2] : 0.f;
                b3 = (bn + bcol + 3 < N) ? bp[3] : 0.f;
            }
        }

        // compute 8 k-steps
#pragma unroll
        for (int k = 0; k < 8; ++k) {
            float ar[8], br[8];
            *reinterpret_cast<float4*>(&ar[0]) = *reinterpret_cast<float4*>(&As[k][ty * 8]);
            *reinterpret_cast<float4*>(&ar[4]) = *reinterpret_cast<float4*>(&As[k][ty * 8 + 4]);
            *reinterpret_cast<float4*>(&br[0]) = *reinterpret_cast<float4*>(&Bs[k][tx * 8]);
            *reinterpret_cast<float4*>(&br[4]) = *reinterpret_cast<float4*>(&Bs[k][tx * 8 + 4]);
#pragma unroll
            for (int i = 0; i < 8; ++i)
#pragma unroll
                for (int j = 0; j < 8; ++j)
                    acc[i][j] += ar[i] * br[j];
        }
        __syncthreads();
    }

    // epilogue
#pragma unroll
    for (int i = 0; i < 8; ++i) {
        const int r = bm + ty * 8 + i;
        if (r < M) {
#pragma unroll
            for (int j = 0; j < 8; ++j) {
                const int cn = bn + tx * 8 + j;
                if (cn < N) {
                    float v = acc[i][j] + bias[cn];
                    if (relu) v = fmaxf(v, 0.f);
                    C[(size_t)r * N + cn] = v;
                }
            }
        }
    }
}

// ------------------------- softmax over 91 classes, 1 warp/row -------------------------
__global__ void softmax_kernel()
{
    const int n    = blockIdx.x;
    const int lane = threadIdx.x;   // 32 threads

    float v[3];
    float mx = -3.4e38f;
#pragma unroll
    for (int t = 0; t < 3; ++t) {
        const int i = lane + 32 * t;
        v[t] = (i < NCLS) ? g_logits[n * NCLS + i] : -3.4e38f;
        mx = fmaxf(mx, v[t]);
    }
#pragma unroll
    for (int s = 16; s > 0; s >>= 1)
        mx = fmaxf(mx, __shfl_xor_sync(0xffffffffu, mx, s));

    float sum = 0.f;
#pragma unroll
    for (int t = 0; t < 3; ++t) {
        const int i = lane + 32 * t;
        if (i < NCLS) { v[t] = expf(v[t] - mx); sum += v[t]; }
    }
#pragma unroll
    for (int s = 16; s > 0; s >>= 1)
        sum += __shfl_xor_sync(0xffffffffu, sum, s);

#pragma unroll
    for (int t = 0; t < 3; ++t) {
        const int i = lane + 32 * t;
        if (i < NCLS) g_scores[n * NCLS + i] = v[t] / sum;
    }
}

// ------------------------- decode + clip + valid mask -------------------------
__global__ void decode_kernel(const float* __restrict__ proposals,
                              const int* __restrict__ imh, const int* __restrict__ imw)
{
    const int idx = blockIdx.x * blockDim.x + threadIdx.x;
    if (idx >= TOT) return;

    const int n = idx / NC1;
    const int c = idx % NC1 + 1;

    const float Wim = (float)(*imw);
    const float Him = (float)(*imh);

    const float4 p = *reinterpret_cast<const float4*>(&proposals[n * 4]);
    const float pw  = p.z - p.x;
    const float ph  = p.w - p.y;
    const float pcx = p.x + 0.5f * pw;
    const float pcy = p.y + 0.5f * ph;

    const float4 r = *reinterpret_cast<const float4*>(&g_breg[n * (4 * NCLS) + c * 4]);
    const float dx = r.x / 10.0f;
    const float dy = r.y / 10.0f;
    const float dw = fminf(r.z / 5.0f, BBOX_CLIP_F);
    const float dh = fminf(r.w / 5.0f, BBOX_CLIP_F);

    const float cx = dx * pw + pcx;
    const float cy = dy * ph + pcy;
    const float w  = expf(dw) * pw;
    const float hh = expf(dh) * ph;

    float x1 = cx - 0.5f * w;
    float y1 = cy - 0.5f * hh;
    float x2 = cx + 0.5f * w;
    float y2 = cy + 0.5f * hh;

    x1 = fminf(fmaxf(x1, 0.f), Wim);
    y1 = fminf(fmaxf(y1, 0.f), Him);
    x2 = fminf(fmaxf(x2, 0.f), Wim);
    y2 = fminf(fmaxf(y2, 0.f), Him);

    const float score = g_scores[n * NCLS + c];
    const float bw = x2 - x1;
    const float bh = y2 - y1;
    const bool valid = (score > 0.05f) && (bw >= 0.01f) && (bh >= 0.01f);

    float4 ob; ob.x = x1; ob.y = y1; ob.z = x2; ob.w = y2;
    *reinterpret_cast<float4*>(&g_dbox[idx * 4]) = ob;
    g_valid[idx] = valid ? 1 : 0;
}

// ------------------------- deterministic order-preserving compaction -------------------------
__global__ void __launch_bounds__(1024) compact_kernel(const int* __restrict__ imh,
                                                       const int* __restrict__ imw)
{
    __shared__ int wsum[32];
    __shared__ int woff[32];
    __shared__ int chunk_total;
    __shared__ int sbase;

    const int tid  = threadIdx.x;
    const int lane = tid & 31;
    const int w    = tid >> 5;

    const float Wim = (float)(*imw);
    const float Him = (float)(*imh);
    const float offscale = fmaxf(Wim, Him) + 1.0f;

    if (tid == 0) sbase = 0;
    __syncthreads();

    for (int c0 = 0; c0 < TOT; c0 += 1024) {
        const int idx = c0 + tid;
        const int flag = (idx < TOT) ? (int)g_valid[idx] : 0;

        const unsigned ball = __ballot_sync(0xffffffffu, flag != 0);
        const int wpre = __popc(ball & ((1u << lane) - 1u));
        if (lane == 0) wsum[w] = __popc(ball);
        __syncthreads();

        if (w == 0) {
            int v = wsum[lane];
            int incl = v;
#pragma unroll
            for (int d = 1; d < 32; d <<= 1) {
                int t = __shfl_up_sync(0xffffffffu, incl, d);
                if (lane >= d) incl += t;
            }
            woff[lane] = incl - v;
            if (lane == 31) chunk_total = incl;
        }
        __syncthreads();

        if (flag) {
            const int pos = sbase + woff[w] + wpre;
            if (pos < MAXC) {
                const int n = idx / NC1;
                const int c = idx % NC1 + 1;
                const float4 b = *reinterpret_cast<const float4*>(&g_dbox[idx * 4]);
                *reinterpret_cast<float4*>(&g_cbox[pos * 4]) = b;
                const float ov = (float)c * offscale;
                float4 ob; ob.x = b.x + ov; ob.y = b.y + ov; ob.z = b.z + ov; ob.w = b.w + ov;
                *reinterpret_cast<float4*>(&g_obox[pos * 4]) = ob;
                const float s = g_scores[n * NCLS + c];
                g_csm[pos]    = s;
                g_cscore[pos] = s;
                g_clabel[pos] = c;
            }
        }
        __syncthreads();
        if (tid == 0) sbase += chunk_total;
        __syncthreads();
    }
    if (tid == 0) g_ccount = (sbase < MAXC) ? sbase : MAXC;
}

// ------------------------- greedy NMS (single block, scores in smem) -------------------------
__global__ void __launch_bounds__(1024) nms_kernel()
{
    extern __shared__ float smv[];       // [M] masked scores
    __shared__ float redv[1024];
    __shared__ int   redi[1024];
    __shared__ float bbox[4];
    __shared__ float barea;
    __shared__ float bval_s;
    __shared__ int   bidx_s;

    const int tid = threadIdx.x;
    const int M   = g_ccount;

    for (int j = tid; j < M; j += 1024) smv[j] = g_csm[j];
    if (tid < MAXDET) g_keep[tid] = -1;
    __syncthreads();

    for (int it = 0; it < MAXDET; ++it) {
        // argmax (first occurrence of max, matching jnp.argmax)
        float bv = -2e10f;
        int   bi = 0x7fffffff;
        for (int j = tid; j < M; j += 1024) {
            const float v = smv[j];
            if (v > bv || (v == bv && j < bi)) { bv = v; bi = j; }
        }
        redv[tid] = bv; redi[tid] = bi;
        __syncthreads();
        for (int s = 512; s > 0; s >>= 1) {
            if (tid < s) {
                const float v2 = redv[tid + s];
                const int   i2 = redi[tid + s];
                if (v2 > redv[tid] || (v2 == redv[tid] && i2 < redi[tid])) {
                    redv[tid] = v2; redi[tid] = i2;
                }
            }
            __syncthreads();
        }
        if (tid == 0) {
            bval_s = redv[0];
            bidx_s = redi[0];
            if (redv[0] > NEGV * 0.5f) {
                g_keep[it] = redi[0];
                const float4 b = *reinterpret_cast<const float4*>(&g_obox[redi[0] * 4]);
                bbox[0] = b.x; bbox[1] = b.y; bbox[2] = b.z; bbox[3] = b.w;
                barea = (b.z - b.x) * (b.w - b.y);
            }
        }
        __syncthreads();

        if (bval_s <= NEGV * 0.5f) break;

        const float bx1 = bbox[0], by1 = bbox[1], bx2 = bbox[2], by2 = bbox[3];
        const float ai  = barea;
        const int bidx  = bidx_s;

        for (int j = tid; j < M; j += 1024) {
            const float4 o = *reinterpret_cast<const float4*>(&g_obox[j * 4]);
            const float xx1 = fmaxf(bx1, o.x);
            const float yy1 = fmaxf(by1, o.y);
            const float xx2 = fminf(bx2, o.z);
            const float yy2 = fminf(by2, o.w);
            const float iw = fmaxf(xx2 - xx1, 0.f);
            const float ih = fmaxf(yy2 - yy1, 0.f);
            const float inter = iw * ih;
            const float aj = (o.z - o.x) * (o.w - o.y);
            const float iou = inter / (ai + aj - inter + 1e-9f);
            if (iou > 0.5f || j == bidx) smv[j] = NEGV;
        }
        __syncthreads();
    }
}

// ------------------------- gather outputs -------------------------
__global__ void gather_kernel(float* __restrict__ out, int out_size)
{
    const int j = threadIdx.x;
    if (j >= MAXDET) return;
    const int k = g_keep[j];
    float b0 = 0, b1 = 0, b2 = 0, b3 = 0, s = 0, l = 0;
    if (k >= 0) {
        b0 = g_cbox[k * 4 + 0];
        b1 = g_cbox[k * 4 + 1];
        b2 = g_cbox[k * 4 + 2];
        b3 = g_cbox[k * 4 + 3];
        s  = g_cscore[k];
        l  = (float)g_clabel[k];
    }
    if (j * 4 + 3 < out_size) {
        out[j * 4 + 0] = b0;
        out[j * 4 + 1] = b1;
        out[j * 4 + 2] = b2;
        out[j * 4 + 3] = b3;
    }
    if (4 * MAXDET + j < out_size) out[4 * MAXDET + j] = s;
    if (5 * MAXDET + j < out_size) out[5 * MAXDET + j] = l;
}

// ------------------------- launch -------------------------
extern "C" void kernel_launch(void* const* d_in, const int* in_sizes, int n_in,
                              void* d_out, int out_size)
{
    const float* X  = (const float*)d_in[0];
    const float* P  = (const float*)d_in[1];
    const float* W1 = (const float*)d_in[2];
    const float* b1 = (const float*)d_in[3];
    const float* W2 = (const float*)d_in[4];
    const float* b2 = (const float*)d_in[5];
    const float* Wc = (const float*)d_in[6];
    const float* bc = (const float*)d_in[7];
    const float* Wr = (const float*)d_in[8];
    const float* br = (const float*)d_in[9];
    const int* imh  = (const int*)d_in[10];
    const int* imw  = (const int*)d_in[11];

    float *p_h1, *p_h2, *p_logits, *p_breg;
    cudaGetSymbolAddress((void**)&p_h1, g_h1);
    cudaGetSymbolAddress((void**)&p_h2, g_h2);
    cudaGetSymbolAddress((void**)&p_logits, g_logits);
    cudaGetSymbolAddress((void**)&p_breg, g_breg);

    // h1 = relu(X @ W1 + b1)    [2000 x 1024]
    sgemm_bias_act<<<dim3(REP / 128, (N_ROIS + 127) / 128), 256>>>(
        X, W1, b1, p_h1, N_ROIS, REP, IN_F, 1);
    // h2 = relu(h1 @ W2 + b2)   [2000 x 1024]
    sgemm_bias_act<<<dim3(REP / 128, (N_ROIS + 127) / 128), 256>>>(
        p_h1, W2, b2, p_h2, N_ROIS, REP, REP, 1);
    // logits = h2 @ Wc + bc     [2000 x 91]
    sgemm_bias_act<<<dim3(1, (N_ROIS + 127) / 128), 256>>>(
        p_h2, Wc, bc, p_logits, N_ROIS, NCLS, REP, 0);
    // breg = h2 @ Wr + br       [2000 x 364]
    sgemm_bias_act<<<dim3(3, (N_ROIS + 127) / 128), 256>>>(
        p_h2, Wr, br, p_breg, N_ROIS, 4 * NCLS, REP, 0);

    softmax_kernel<<<N_ROIS, 32>>>();
    decode_kernel<<<(TOT + 255) / 256, 256>>>(P, imh, imw);
    compact_kernel<<<1, 1024>>>(imh, imw);

    cudaFuncSetAttribute(nms_kernel, cudaFuncAttributeMaxDynamicSharedMemorySize, MAXC * 4);
    nms_kernel<<<1, 1024, MAXC * 4>>>();

    gather_kernel<<<1, 128>>>((float*)d_out, out_size);
}

// round 5
// speedup vs baseline: 2.8727x; 2.8727x over previous
#include <cuda_runtime.h>
#include <cuda_fp16.h>
#include <math.h>
#include <stdint.h>

#define N_ROIS 2000
#define MPAD   2048
#define IN_F   12544
#define REP    1024
#define NHEAD  512
#define NCLS   91
#define NC1    90
#define NPAD   2048
#define NEGV   (-1e10f)
#define BBOX_CLIP_F 4.135166556742356f
#define MAXDET 100
#define INV2048 4.8828125e-4f

// ======================= static scratch (no allocs; zero-initialized) =======================
__device__ __half gA_hi[MPAD * IN_F];
__device__ __half gA_lo[MPAD * IN_F];
__device__ __half gW1_hi[REP * IN_F];
__device__ __half gW1_lo[REP * IN_F];
__device__ __half gW2_hi[REP * REP];
__device__ __half gW2_lo[REP * REP];
__device__ __half gWh_hi[NHEAD * REP];
__device__ __half gWh_lo[NHEAD * REP];
__device__ __half gH1_hi[MPAD * REP];
__device__ __half gH1_lo[MPAD * REP];
__device__ __half gH2_hi[MPAD * REP];
__device__ __half gH2_lo[MPAD * REP];
__device__ float gBiasH[NHEAD];
__device__ float g_comb[N_ROIS * NHEAD];     // logits cols 0..90, breg cols 92+4c
__device__ float g_scores[N_ROIS * NCLS];
__device__ unsigned long long g_surv[NC1 * MAXDET];
__device__ int g_snum[NC1];

// ======================= helpers =======================
__device__ __forceinline__ uint32_t s2u(const void* p) {
    uint32_t a;
    asm("{ .reg .u64 t; cvta.to.shared.u64 t, %1; cvt.u32.u64 %0, t; }" : "=r"(a) : "l"(p));
    return a;
}
__device__ __forceinline__ void ldm4(uint32_t* r, uint32_t addr) {
    asm volatile("ldmatrix.sync.aligned.m8n8.x4.shared.b16 {%0,%1,%2,%3}, [%4];"
                 : "=r"(r[0]), "=r"(r[1]), "=r"(r[2]), "=r"(r[3]) : "r"(addr));
}
__device__ __forceinline__ void mma_f16(float* d, const uint32_t* a, const uint32_t* b) {
    asm volatile(
        "mma.sync.aligned.m16n8k16.row.col.f32.f16.f16.f32 "
        "{%0,%1,%2,%3}, {%4,%5,%6,%7}, {%8,%9}, {%0,%1,%2,%3};"
        : "+f"(d[0]), "+f"(d[1]), "+f"(d[2]), "+f"(d[3])
        : "r"(a[0]), "r"(a[1]), "r"(a[2]), "r"(a[3]), "r"(b[0]), "r"(b[1]));
}
__device__ __forceinline__ void split2(float x, __half& h, __half& l) {
    h = __float2half_rn(x);
    float r = x - __half2float(h);
    l = __float2half_rn(r * 2048.0f);
}
__device__ __forceinline__ void decode_one(
    int n, int c, const float* __restrict__ P, float Wim, float Him,
    float& x1, float& y1, float& x2, float& y2)
{
    const float4 p = *reinterpret_cast<const float4*>(&P[n * 4]);
    const float pw = p.z - p.x;
    const float ph = p.w - p.y;
    const float pcx = p.x + 0.5f * pw;
    const float pcy = p.y + 0.5f * ph;
    const float4 r = *reinterpret_cast<const float4*>(&g_comb[(size_t)n * NHEAD + 92 + c * 4]);
    const float dx = r.x / 10.0f;
    const float dy = r.y / 10.0f;
    const float dw = fminf(r.z / 5.0f, BBOX_CLIP_F);
    const float dh = fminf(r.w / 5.0f, BBOX_CLIP_F);
    const float cx = dx * pw + pcx;
    const float cy = dy * ph + pcy;
    const float w = expf(dw) * pw;
    const float hh = expf(dh) * ph;
    x1 = fminf(fmaxf(cx - 0.5f * w, 0.f), Wim);
    y1 = fminf(fmaxf(cy - 0.5f * hh, 0.f), Him);
    x2 = fminf(fmaxf(cx + 0.5f * w, 0.f), Wim);
    y2 = fminf(fmaxf(cy + 0.5f * hh, 0.f), Him);
}

// ======================= pre-pass kernels =======================
__global__ void split_X(const float* __restrict__ X) {
    const int idx = blockIdx.x * 256 + threadIdx.x;   // one float4
    if (idx >= N_ROIS * IN_F / 4) return;
    const size_t e = (size_t)idx * 4;
    const float4 v = *(const float4*)(X + e);
    __half h0, l0, h1, l1, h2, l2, h3, l3;
    split2(v.x, h0, l0); split2(v.y, h1, l1);
    split2(v.z, h2, l2); split2(v.w, h3, l3);
    __half2 t;
    t.x = h0; t.y = h1; *(__half2*)(gA_hi + e) = t;
    t.x = h2; t.y = h3; *(__half2*)(gA_hi + e + 2) = t;
    t.x = l0; t.y = l1; *(__half2*)(gA_lo + e) = t;
    t.x = l2; t.y = l3; *(__half2*)(gA_lo + e + 2) = t;
}

// transpose + split: W [K x N] fp32 -> out [N x K] fp16 x2
__global__ void tsplitW(const float* __restrict__ W,
                        __half* __restrict__ Oh, __half* __restrict__ Ol, int K, int N) {
    __shared__ float t[32][33];
    const int k0 = blockIdx.x * 32, n0 = blockIdx.y * 32;
    const int tx = threadIdx.x, ty = threadIdx.y;
#pragma unroll
    for (int i = 0; i < 4; ++i)
        t[ty + 8 * i][tx] = W[(size_t)(k0 + ty + 8 * i) * N + n0 + tx];
    __syncthreads();
#pragma unroll
    for (int i = 0; i < 4; ++i) {
        const float v = t[tx][ty + 8 * i];
        __half h, l;
        split2(v, h, l);
        const size_t o = (size_t)(n0 + ty + 8 * i) * K + k0 + tx;
        Oh[o] = h; Ol[o] = l;
    }
}

__global__ void build_head(const float* __restrict__ Wc, const float* __restrict__ Wr) {
    const int n = blockIdx.x;
    const int k = blockIdx.y * 256 + threadIdx.x;
    float v = 0.f;
    if (n < NCLS) v = Wc[(size_t)k * NCLS + n];
    else if (n >= 92 && n < 92 + 4 * NCLS) v = Wr[(size_t)k * (4 * NCLS) + (n - 92)];
    __half h, l;
    split2(v, h, l);
    const size_t o = (size_t)n * REP + k;
    gWh_hi[o] = h; gWh_lo[o] = l;
}

__global__ void build_bias(const float* __restrict__ bc, const float* __restrict__ br) {
    const int c = blockIdx.x * 256 + threadIdx.x;
    if (c >= NHEAD) return;
    float v = 0.f;
    if (c < NCLS) v = bc[c];
    else if (c >= 92 && c < 92 + 4 * NCLS) v = br[c - 92];
    gBiasH[c] = v;
}

// ======================= HMMA GEMM =======================
// C[M,N] = A[M,K] @ B[N,K]^T with fp32-equivalent precision via fp16 2-way split.
// A/B lo arrays are pre-scaled by 2^11. acc = accM + accC/2048.
#define STAGE_B 32768
#define SMEM_GEMM (3 * STAGE_B)

__global__ void __launch_bounds__(256, 1) hgemm(
    const __half* __restrict__ Ah, const __half* __restrict__ Al,
    const __half* __restrict__ Bh, const __half* __restrict__ Bl,
    const float* __restrict__ bias, int K, int Mreal, int mode,
    float* __restrict__ C, int ldc,
    __half* __restrict__ Oh, __half* __restrict__ Ol, int ldo)
{
    extern __shared__ __align__(16) char smem[];
    const uint32_t sb = s2u(smem);
    const int tid = threadIdx.x;
    const int lane = tid & 31, wid = tid >> 5;
    const int wm = wid & 1, wn = wid >> 1;           // warp tile: 64x32 at (wm*64, wn*32)
    const int bm = blockIdx.y * 128, bn = blockIdx.x * 128;
    const int niter = K >> 5;

    float accM[4][4][4], accC[4][4][4];
#pragma unroll
    for (int m = 0; m < 4; ++m)
#pragma unroll
        for (int n = 0; n < 4; ++n)
#pragma unroll
            for (int e = 0; e < 4; ++e) { accM[m][n][e] = 0.f; accC[m][n][e] = 0.f; }

    auto load_stage = [&](int st, int k0) {
#pragma unroll
        for (int j = 0; j < 8; ++j) {
            const int q = j * 256 + tid;
            const int isB = q >> 10;
            const int sp = (q >> 9) & 1;
            const int row = (q >> 2) & 127;
            const int seg = q & 3;
            uint32_t rel = (uint32_t)(row * 128 + sp * 64 + seg * 16);
            rel ^= (rel >> 3) & 0x70;
            const uint32_t dst = sb + (uint32_t)st * STAGE_B + (uint32_t)isB * 16384 + rel;
            const __half* src;
            if (isB) src = (sp ? Bl : Bh) + (size_t)(bn + row) * K + k0 + seg * 8;
            else     src = (sp ? Al : Ah) + (size_t)(bm + row) * K + k0 + seg * 8;
            asm volatile("cp.async.cg.shared.global [%0], [%1], 16;" :: "r"(dst), "l"(src));
        }
    };

    auto compute_stage = [&](int st) {
        const uint32_t ab = sb + (uint32_t)st * STAGE_B;
        const uint32_t bb = ab + 16384;
#pragma unroll
        for (int kk = 0; kk < 2; ++kk) {
            uint32_t Af[4][4], Lf[4][4], Bf[4][2], Mf[4][2];
#pragma unroll
            for (int m = 0; m < 4; ++m) {
                const int row = wm * 64 + m * 16 + (lane & 15);
                const int colb = kk * 32 + ((lane >> 4) << 4);
                uint32_t r1 = (uint32_t)(row * 128 + colb);
                uint32_t r2 = (uint32_t)(row * 128 + 64 + colb);
                r1 ^= (r1 >> 3) & 0x70;
                r2 ^= (r2 >> 3) & 0x70;
                ldm4(Af[m], ab + r1);
                ldm4(Lf[m], ab + r2);
            }
#pragma unroll
            for (int p = 0; p < 2; ++p) {
                const int mm = lane >> 3;
                const int row = wn * 32 + p * 16 + ((mm >> 1) << 3) + (lane & 7);
                const int colb = kk * 32 + ((mm & 1) << 4);
                uint32_t r1 = (uint32_t)(row * 128 + colb);
                uint32_t r2 = (uint32_t)(row * 128 + 64 + colb);
                r1 ^= (r1 >> 3) & 0x70;
                r2 ^= (r2 >> 3) & 0x70;
                uint32_t t[4];
                ldm4(t, bb + r1);
                Bf[2 * p][0] = t[0]; Bf[2 * p][1] = t[1];
                Bf[2 * p + 1][0] = t[2]; Bf[2 * p + 1][1] = t[3];
                ldm4(t, bb + r2);
                Mf[2 * p][0] = t[0]; Mf[2 * p][1] = t[1];
                Mf[2 * p + 1][0] = t[2]; Mf[2 * p + 1][1] = t[3];
            }
#pragma unroll
            for (int m = 0; m < 4; ++m)
#pragma unroll
                for (int n = 0; n < 4; ++n) {
                    mma_f16(accM[m][n], Af[m], Bf[n]);
                    mma_f16(accC[m][n], Af[m], Mf[n]);
                    mma_f16(accC[m][n], Lf[m], Bf[n]);
                }
        }
    };

    for (int p = 0; p < 3; ++p) {
        if (p < niter) load_stage(p, p * 32);
        asm volatile("cp.async.commit_group;" ::: "memory");
    }
    for (int i = 0; i < niter; ++i) {
        asm volatile("cp.async.wait_group 2;" ::: "memory");
        __syncthreads();
        compute_stage(i % 3);
        __syncthreads();
        const int nxt = i + 3;
        if (nxt < niter) load_stage(nxt % 3, nxt * 32);
        asm volatile("cp.async.commit_group;" ::: "memory");
    }
    asm volatile("cp.async.wait_group 0;" ::: "memory");

    // epilogue
    const int rb = bm + wm * 64 + (lane >> 2);
    const int cb = bn + wn * 32 + 2 * (lane & 3);
#pragma unroll
    for (int m = 0; m < 4; ++m) {
#pragma unroll
        for (int n = 0; n < 4; ++n) {
            const int cc = cb + n * 8;
            const float2 bi = *(const float2*)&bias[cc];
#pragma unroll
            for (int half = 0; half < 2; ++half) {
                const int r = rb + m * 16 + half * 8;
                if (r < Mreal) {
                    float v0 = accM[m][n][2 * half + 0] + accC[m][n][2 * half + 0] * INV2048 + bi.x;
                    float v1 = accM[m][n][2 * half + 1] + accC[m][n][2 * half + 1] * INV2048 + bi.y;
                    if (mode == 0) {
                        float2 o; o.x = v0; o.y = v1;
                        *(float2*)&C[(size_t)r * ldc + cc] = o;
                    } else {
                        v0 = fmaxf(v0, 0.f);
                        v1 = fmaxf(v1, 0.f);
                        __half h0, l0, h1, l1;
                        split2(v0, h0, l0);
                        split2(v1, h1, l1);
                        __half2 th; th.x = h0; th.y = h1;
                        __half2 tl; tl.x = l0; tl.y = l1;
                        *(__half2*)&Oh[(size_t)r * ldo + cc] = th;
                        *(__half2*)&Ol[(size_t)r * ldo + cc] = tl;
                    }
                }
            }
        }
    }
}

// ======================= softmax =======================
__global__ void softmax_kernel() {
    const int n = blockIdx.x;
    const int lane = threadIdx.x;
    float v[3];
    float mx = -3.4e38f;
#pragma unroll
    for (int t = 0; t < 3; ++t) {
        const int i = lane + 32 * t;
        v[t] = (i < NCLS) ? g_comb[(size_t)n * NHEAD + i] : -3.4e38f;
        mx = fmaxf(mx, v[t]);
    }
#pragma unroll
    for (int s = 16; s > 0; s >>= 1) mx = fmaxf(mx, __shfl_xor_sync(0xffffffffu, mx, s));
    float sum = 0.f;
#pragma unroll
    for (int t = 0; t < 3; ++t) {
        const int i = lane + 32 * t;
        if (i < NCLS) { v[t] = expf(v[t] - mx); sum += v[t]; }
    }
#pragma unroll
    for (int s = 16; s > 0; s >>= 1) sum += __shfl_xor_sync(0xffffffffu, sum, s);
#pragma unroll
    for (int t = 0; t < 3; ++t) {
        const int i = lane + 32 * t;
        if (i < NCLS) g_scores[n * NCLS + i] = v[t] / sum;
    }
}

// ======================= per-class NMS =======================
// Class offsets make cross-class IoU exactly 0, so global greedy NMS ==
// per-class greedy NMS merged by (score desc, flat idx asc).
#define CSMEM (4 * NPAD * 4 + NPAD * 8 + NPAD)

__global__ void __launch_bounds__(256) class_nms(
    const float* __restrict__ P, const int* __restrict__ imh, const int* __restrict__ imw)
{
    extern __shared__ __align__(16) char smemraw[];
    float* sx1 = (float*)smemraw;
    float* sy1 = sx1 + NPAD;
    float* sx2 = sy1 + NPAD;
    float* sy2 = sx2 + NPAD;
    unsigned long long* keys = (unsigned long long*)(sy2 + NPAD);
    char* alive = (char*)(keys + NPAD);
    __shared__ int s_nsurv;

    const int tid = threadIdx.x;
    const int cls = blockIdx.x;        // 0..89
    const int c = cls + 1;             // label
    const float Wim = (float)(*imw);
    const float Him = (float)(*imh);
    const float offv = (float)c * (fmaxf(Wim, Him) + 1.0f);

    if (tid == 0) s_nsurv = 0;

    for (int n = tid; n < NPAD; n += 256) {
        unsigned long long key = 0ull;
        if (n < N_ROIS) {
            float x1, y1, x2, y2;
            decode_one(n, c, P, Wim, Him, x1, y1, x2, y2);
            const float s = g_scores[n * NCLS + c];
            if (s > 0.05f && (x2 - x1) >= 0.01f && (y2 - y1) >= 0.01f) {
                sx1[n] = x1 + offv;
                sy1[n] = y1 + offv;
                sx2[n] = x2 + offv;
                sy2[n] = y2 + offv;
                key = ((unsigned long long)__float_as_uint(s) << 32)
                    | (unsigned long long)(0xFFFFFFFFu - (unsigned)n);
            }
        }
        keys[n] = key;
        alive[n] = 1;
    }
    __syncthreads();

    // bitonic sort descending (score desc, n asc via ~n in low bits)
    for (int k = 2; k <= NPAD; k <<= 1) {
        for (int j = k >> 1; j > 0; j >>= 1) {
            for (int i = tid; i < NPAD; i += 256) {
                const int l = i ^ j;
                if (l > i) {
                    const unsigned long long a = keys[i], b = keys[l];
                    const bool up = ((i & k) == 0);
                    if (up ? (a < b) : (a > b)) { keys[i] = b; keys[l] = a; }
                }
            }
            __syncthreads();
        }
    }

    // greedy NMS in sorted order
    for (int pos = 0; pos < NPAD; ++pos) {
        const unsigned long long k = keys[pos];
        if (k == 0ull) break;
        if (!alive[pos]) continue;
        if (s_nsurv >= MAXDET) break;
        const int ni = (int)(0xFFFFFFFFu - (unsigned)(k & 0xFFFFFFFFull));
        const float bx1 = sx1[ni], by1 = sy1[ni], bx2 = sx2[ni], by2 = sy2[ni];
        const float ai = (bx2 - bx1) * (by2 - by1);
        if (tid == 0) {
            const unsigned flat = (unsigned)(ni * NC1 + cls);
            g_surv[cls * MAXDET + s_nsurv] =
                (k & 0xFFFFFFFF00000000ull) | (unsigned long long)(0xFFFFFFFFu - flat);
            s_nsurv++;
        }
        for (int j = pos + 1 + tid; j < NPAD; j += 256) {
            if (!alive[j]) continue;
            const unsigned long long k2 = keys[j];
            if (k2 == 0ull) continue;
            const int nj = (int)(0xFFFFFFFFu - (unsigned)(k2 & 0xFFFFFFFFull));
            const float xx1 = fmaxf(bx1, sx1[nj]);
            const float yy1 = fmaxf(by1, sy1[nj]);
            const float xx2 = fminf(bx2, sx2[nj]);
            const float yy2 = fminf(by2, sy2[nj]);
            const float inter = fmaxf(xx2 - xx1, 0.f) * fmaxf(yy2 - yy1, 0.f);
            const float aj = (sx2[nj] - sx1[nj]) * (sy2[nj] - sy1[nj]);
            const float iou = inter / (ai + aj - inter + 1e-9f);
            if (iou > 0.5f) alive[j] = 0;
        }
        __syncthreads();
    }
    __syncthreads();
    if (tid == 0) g_snum[cls] = s_nsurv;
}

// ======================= merge + output =======================
__global__ void __launch_bounds__(128) final_select(
    const float* __restrict__ P, const int* __restrict__ imh, const int* __restrict__ imw,
    float* __restrict__ out, int out_size)
{
    __shared__ unsigned long long red[128];
    __shared__ int heads[NC1];
    __shared__ int cnts[NC1];
    __shared__ int keep[MAXDET];
    __shared__ int s_w;

    const int tid = threadIdx.x;
    if (tid < NC1) { heads[tid] = 0; cnts[tid] = g_snum[tid]; }
    if (tid < MAXDET) keep[tid] = -1;
    __syncthreads();

    for (int it = 0; it < MAXDET; ++it) {
        unsigned long long cand = 0ull;
        if (tid < NC1 && heads[tid] < cnts[tid])
            cand = g_surv[tid * MAXDET + heads[tid]];
        red[tid] = cand;
        __syncthreads();
        for (int s = 64; s > 0; s >>= 1) {
            if (tid < s) { if (red[tid + s] > red[tid]) red[tid] = red[tid + s]; }
            __syncthreads();
        }
        const unsigned long long best = red[0];
        if (best == 0ull) break;
        if (tid < NC1 && cand == best) s_w = tid;
        __syncthreads();
        if (tid == 0) {
            heads[s_w]++;
            keep[it] = (int)(0xFFFFFFFFu - (unsigned)(best & 0xFFFFFFFFull));
        }
        __syncthreads();
    }

    if (tid < MAXDET) {
        const int k = keep[tid];
        float b0 = 0, b1 = 0, b2 = 0, b3 = 0, s = 0, l = 0;
        if (k >= 0) {
            const int n = k / NC1;
            const int c = k % NC1 + 1;
            const float Wim = (float)(*imw);
            const float Him = (float)(*imh);
            float x1, y1, x2, y2;
            decode_one(n, c, P, Wim, Him, x1, y1, x2, y2);
            b0 = x1; b1 = y1; b2 = x2; b3 = y2;
            s = g_scores[n * NCLS + c];
            l = (float)c;
        }
        if (tid * 4 + 3 < out_size) {
            out[tid * 4 + 0] = b0;
            out[tid * 4 + 1] = b1;
            out[tid * 4 + 2] = b2;
            out[tid * 4 + 3] = b3;
        }
        if (4 * MAXDET + tid < out_size) out[4 * MAXDET + tid] = s;
        if (5 * MAXDET + tid < out_size) out[5 * MAXDET + tid] = l;
    }
}

// ======================= launch =======================
extern "C" void kernel_launch(void* const* d_in, const int* in_sizes, int n_in,
                              void* d_out, int out_size) {
    const float* X  = (const float*)d_in[0];
    const float* P  = (const float*)d_in[1];
    const float* W1 = (const float*)d_in[2];
    const float* b1 = (const float*)d_in[3];
    const float* W2 = (const float*)d_in[4];
    const float* b2 = (const float*)d_in[5];
    const float* Wc = (const float*)d_in[6];
    const float* bc = (const float*)d_in[7];
    const float* Wr = (const float*)d_in[8];
    const float* br = (const float*)d_in[9];
    const int* imh  = (const int*)d_in[10];
    const int* imw  = (const int*)d_in[11];

    __half *pAh, *pAl, *pW1h, *pW1l, *pW2h, *pW2l, *pWhh, *pWhl;
    __half *pH1h, *pH1l, *pH2h, *pH2l;
    float *pBiasH, *pComb;
    cudaGetSymbolAddress((void**)&pAh, gA_hi);
    cudaGetSymbolAddress((void**)&pAl, gA_lo);
    cudaGetSymbolAddress((void**)&pW1h, gW1_hi);
    cudaGetSymbolAddress((void**)&pW1l, gW1_lo);
    cudaGetSymbolAddress((void**)&pW2h, gW2_hi);
    cudaGetSymbolAddress((void**)&pW2l, gW2_lo);
    cudaGetSymbolAddress((void**)&pWhh, gWh_hi);
    cudaGetSymbolAddress((void**)&pWhl, gWh_lo);
    cudaGetSymbolAddress((void**)&pH1h, gH1_hi);
    cudaGetSymbolAddress((void**)&pH1l, gH1_lo);
    cudaGetSymbolAddress((void**)&pH2h, gH2_hi);
    cudaGetSymbolAddress((void**)&pH2l, gH2_lo);
    cudaGetSymbolAddress((void**)&pBiasH, gBiasH);
    cudaGetSymbolAddress((void**)&pComb, g_comb);

    cudaFuncSetAttribute(hgemm, cudaFuncAttributeMaxDynamicSharedMemorySize, SMEM_GEMM);
    cudaFuncSetAttribute(class_nms, cudaFuncAttributeMaxDynamicSharedMemorySize, CSMEM);

    // pre-pass
    split_X<<<(N_ROIS * IN_F / 4 + 255) / 256, 256>>>(X);
    tsplitW<<<dim3(IN_F / 32, REP / 32), dim3(32, 8)>>>(W1, pW1h, pW1l, IN_F, REP);
    tsplitW<<<dim3(REP / 32, REP / 32), dim3(32, 8)>>>(W2, pW2h, pW2l, REP, REP);
    build_head<<<dim3(NHEAD, REP / 256), 256>>>(Wc, Wr);
    build_bias<<<(NHEAD + 255) / 256, 256>>>(bc, br);

    // GEMM1: h1 = relu(X @ W1 + b1)
    hgemm<<<dim3(REP / 128, MPAD / 128), 256, SMEM_GEMM>>>(
        pAh, pAl, pW1h, pW1l, b1, IN_F, N_ROIS, 1, nullptr, 0, pH1h, pH1l, REP);
    // GEMM2: h2 = relu(h1 @ W2 + b2)
    hgemm<<<dim3(REP / 128, MPAD / 128), 256, SMEM_GEMM>>>(
        pH1h, pH1l, pW2h, pW2l, b2, REP, N_ROIS, 1, nullptr, 0, pH2h, pH2l, REP);
    // heads: comb = h2 @ [Wc|pad|Wr] + bias
    hgemm<<<dim3(NHEAD / 128, MPAD / 128), 256, SMEM_GEMM>>>(
        pH2h, pH2l, pWhh, pWhl, pBiasH, REP, N_ROIS, 0, pComb, NHEAD, nullptr, nullptr, 0);

    softmax_kernel<<<N_ROIS, 32>>>();
    class_nms<<<NC1, 256, CSMEM>>>(P, imh, imw);
    final_select<<<1, 128>>>(P, imh, imw, (float*)d_out, out_size);
}